// round 1
// baseline (speedup 1.0000x reference)
#include <cuda_runtime.h>
#include <math.h>

#define EPSI 1e-5f
#define GAMMA_C 1.3f

__device__ __forceinline__ float f4c(const float4& v, int i) {
    switch (i & 3) {
        case 0: return v.x;
        case 1: return v.y;
        case 2: return v.z;
        default: return v.w;
    }
}

// Block GEMM: C[32 x 256] = A[32 x KTOT] (smem, row-major, stride lda) * W[KTOT x 256]
// (global, row stride ldw floats). 256 threads. Thread micro-tile: 4 rows x 8 cols,
// cols = {c0..c0+3, c0+128..c0+131} with c0 = (tid&31)*4  (GLU pairs in-thread).
// Weights streamed through double-buffered smem chunks of [16][256].
template <int KTOT, typename Epi>
__device__ __forceinline__ void gemm_tile(
    const float* __restrict__ As, int lda,
    const float* __restrict__ Wg, int ldw,
    float* __restrict__ wbuf, Epi epi)
{
    const int tid = threadIdx.x;
    const int m0 = (tid >> 5) << 2;
    const int nt = tid & 31;
    constexpr int NCH = KTOT / 16;

    float acc[4][8];
#pragma unroll
    for (int r = 0; r < 4; r++)
#pragma unroll
        for (int j = 0; j < 8; j++) acc[r][j] = 0.f;

    float4* wb4 = reinterpret_cast<float4*>(wbuf);
    // load chunk 0 (16 rows x 256 cols = 1024 float4, 4 per thread)
#pragma unroll
    for (int i = 0; i < 4; i++) {
        int f = tid + 256 * i;
        int k = f >> 6, c = f & 63;
        wb4[f] = reinterpret_cast<const float4*>(Wg + k * ldw)[c];
    }
    __syncthreads();

    const float* A0 = As + (m0 + 0) * lda;
    const float* A1 = As + (m0 + 1) * lda;
    const float* A2 = As + (m0 + 2) * lda;
    const float* A3 = As + (m0 + 3) * lda;

    int cur = 0;
    for (int ch = 0; ch < NCH; ch++) {
        float4 pf[4];
        const bool more = (ch + 1 < NCH);
        if (more) {
            const float* Wn = Wg + (ch + 1) * 16 * ldw;
#pragma unroll
            for (int i = 0; i < 4; i++) {
                int f = tid + 256 * i;
                int k = f >> 6, c = f & 63;
                pf[i] = reinterpret_cast<const float4*>(Wn + k * ldw)[c];
            }
        }
        const float4* wc = wb4 + cur * 1024;
        const int kk = ch * 16;
#pragma unroll
        for (int k4 = 0; k4 < 4; k4++) {
            float4 a0 = *reinterpret_cast<const float4*>(A0 + kk + k4 * 4);
            float4 a1 = *reinterpret_cast<const float4*>(A1 + kk + k4 * 4);
            float4 a2 = *reinterpret_cast<const float4*>(A2 + kk + k4 * 4);
            float4 a3 = *reinterpret_cast<const float4*>(A3 + kk + k4 * 4);
#pragma unroll
            for (int kz = 0; kz < 4; kz++) {
                float4 w0 = wc[(k4 * 4 + kz) * 64 + nt];
                float4 w1 = wc[(k4 * 4 + kz) * 64 + 32 + nt];
                float b0 = f4c(a0, kz), b1 = f4c(a1, kz);
                float b2 = f4c(a2, kz), b3 = f4c(a3, kz);
                acc[0][0] = fmaf(b0, w0.x, acc[0][0]); acc[0][1] = fmaf(b0, w0.y, acc[0][1]);
                acc[0][2] = fmaf(b0, w0.z, acc[0][2]); acc[0][3] = fmaf(b0, w0.w, acc[0][3]);
                acc[0][4] = fmaf(b0, w1.x, acc[0][4]); acc[0][5] = fmaf(b0, w1.y, acc[0][5]);
                acc[0][6] = fmaf(b0, w1.z, acc[0][6]); acc[0][7] = fmaf(b0, w1.w, acc[0][7]);
                acc[1][0] = fmaf(b1, w0.x, acc[1][0]); acc[1][1] = fmaf(b1, w0.y, acc[1][1]);
                acc[1][2] = fmaf(b1, w0.z, acc[1][2]); acc[1][3] = fmaf(b1, w0.w, acc[1][3]);
                acc[1][4] = fmaf(b1, w1.x, acc[1][4]); acc[1][5] = fmaf(b1, w1.y, acc[1][5]);
                acc[1][6] = fmaf(b1, w1.z, acc[1][6]); acc[1][7] = fmaf(b1, w1.w, acc[1][7]);
                acc[2][0] = fmaf(b2, w0.x, acc[2][0]); acc[2][1] = fmaf(b2, w0.y, acc[2][1]);
                acc[2][2] = fmaf(b2, w0.z, acc[2][2]); acc[2][3] = fmaf(b2, w0.w, acc[2][3]);
                acc[2][4] = fmaf(b2, w1.x, acc[2][4]); acc[2][5] = fmaf(b2, w1.y, acc[2][5]);
                acc[2][6] = fmaf(b2, w1.z, acc[2][6]); acc[2][7] = fmaf(b2, w1.w, acc[2][7]);
                acc[3][0] = fmaf(b3, w0.x, acc[3][0]); acc[3][1] = fmaf(b3, w0.y, acc[3][1]);
                acc[3][2] = fmaf(b3, w0.z, acc[3][2]); acc[3][3] = fmaf(b3, w0.w, acc[3][3]);
                acc[3][4] = fmaf(b3, w1.x, acc[3][4]); acc[3][5] = fmaf(b3, w1.y, acc[3][5]);
                acc[3][6] = fmaf(b3, w1.z, acc[3][6]); acc[3][7] = fmaf(b3, w1.w, acc[3][7]);
            }
        }
        if (more) {
            float4* wn = wb4 + (cur ^ 1) * 1024;
#pragma unroll
            for (int i = 0; i < 4; i++) wn[tid + 256 * i] = pf[i];
        }
        __syncthreads();
        cur ^= 1;
    }
    epi(m0, nt << 2, acc);
}

__global__ __launch_bounds__(256, 1)
void tabnet_kernel(
    const float* __restrict__ x,
    const float* __restrict__ bn0_g, const float* __restrict__ bn0_b,
    const float* __restrict__ bn0_m, const float* __restrict__ bn0_v,
    const float* __restrict__ shW,
    const float* __restrict__ sh_g, const float* __restrict__ sh_b,
    const float* __restrict__ sh_m, const float* __restrict__ sh_v,
    const float* __restrict__ stW,
    const float* __restrict__ st_g, const float* __restrict__ st_b,
    const float* __restrict__ st_m, const float* __restrict__ st_v,
    const float* __restrict__ atW,
    const float* __restrict__ at_g, const float* __restrict__ at_b,
    const float* __restrict__ at_m, const float* __restrict__ at_v,
    const float* __restrict__ fW, const float* __restrict__ fb,
    float* __restrict__ out)
{
    extern __shared__ float smem[];
    float* xs    = smem;            // [32][512]  x tile, later z buffer for sparsemax
    float* prior = smem + 16384;    // [32][512]
    float* shb   = smem + 32768;    // [32][128]  GLU(shared step) output
    float* hg    = smem + 36864;    // [32][128]  GLU(step) output (h_d | h_a)
    float* aggs  = smem + 40960;    // [32][64]
    float* wbuf  = smem + 43008;    // 2 x [16][256] weight chunks
    float* bnsc  = smem + 51200;    // [512] bn scale table
    float* bnsh  = smem + 51712;    // [512] bn shift table
    // total 52224 floats = 208896 bytes

    const int tid = threadIdx.x;
    const int row0 = blockIdx.x << 5;

    for (int i = tid; i < 2048; i += 256) aggs[i] = 0.f;

    // bn0 tables: scale = g*rsqrt(v+eps), shift = b - m*scale
    for (int c = tid; c < 512; c += 256) {
        float sc = bn0_g[c] * rsqrtf(bn0_v[c] + EPSI);
        bnsc[c] = sc;
        bnsh[c] = bn0_b[c] - bn0_m[c] * sc;
    }
    __syncthreads();

    // load x tile, apply bn0
    {
        const float4* xg = reinterpret_cast<const float4*>(x) + (size_t)row0 * 128;
        const float4* s4 = reinterpret_cast<const float4*>(bnsc);
        const float4* b4 = reinterpret_cast<const float4*>(bnsh);
        float4* xs4 = reinterpret_cast<float4*>(xs);
#pragma unroll
        for (int i = 0; i < 16; i++) {
            int f = tid + 256 * i;
            int c4 = f & 127;
            float4 v = xg[f];
            float4 s = s4[c4], b = b4[c4];
            v.x = fmaf(v.x, s.x, b.x);
            v.y = fmaf(v.y, s.y, b.y);
            v.z = fmaf(v.z, s.z, b.z);
            v.w = fmaf(v.w, s.w, b.w);
            xs4[f] = v;
        }
    }
    __syncthreads();

    // shared-step bn tables (256 cols, one per thread)
    {
        int c = tid;
        float sc = sh_g[c] * rsqrtf(sh_v[c] + EPSI);
        bnsc[c] = sc;
        bnsh[c] = sh_b[c] - sh_m[c] * sc;
    }

    // GEMM1: sh = GLU(bn(x @ shW))
    gemm_tile<512>(xs, 512, shW, 256, wbuf,
        [&](int m0, int c0, float (&acc)[4][8]) {
#pragma unroll
            for (int r = 0; r < 4; r++)
#pragma unroll
                for (int t = 0; t < 4; t++) {
                    int cu = c0 + t, cw = c0 + 128 + t;
                    float u = fmaf(acc[r][t],     bnsc[cu], bnsh[cu]);
                    float w = fmaf(acc[r][4 + t], bnsc[cw], bnsh[cw]);
                    shb[(m0 + r) * 128 + cu] = u / (1.f + __expf(-w));
                }
        });
    __syncthreads();

    for (int s = 0; s < 3; s++) {
        // step bn tables (256 cols)
        {
            int c = tid;
            float sc = st_g[s * 256 + c] * rsqrtf(st_v[s * 256 + c] + EPSI);
            bnsc[c] = sc;
            bnsh[c] = st_b[s * 256 + c] - st_m[s * 256 + c] * sc;
        }
        // GEMM2: h = GLU(bn(sh @ stW[s])); agg += h_d
        gemm_tile<128>(shb, 128, stW + s * 128 * 256, 256, wbuf,
            [&](int m0, int c0, float (&acc)[4][8]) {
#pragma unroll
                for (int r = 0; r < 4; r++)
#pragma unroll
                    for (int t = 0; t < 4; t++) {
                        int cu = c0 + t, cw = c0 + 128 + t;
                        float u = fmaf(acc[r][t],     bnsc[cu], bnsh[cu]);
                        float w = fmaf(acc[r][4 + t], bnsc[cw], bnsh[cw]);
                        float val = u / (1.f + __expf(-w));
                        hg[(m0 + r) * 128 + cu] = val;
                        if (cu < 64) aggs[(m0 + r) * 64 + cu] += val;
                    }
            });
        __syncthreads();
        if (s == 2) break;  // last step's attention/sparsemax/prior affect nothing

        // attention bn tables (512 cols)
        for (int c = tid; c < 512; c += 256) {
            float sc = at_g[s * 512 + c] * rsqrtf(at_v[s * 512 + c] + EPSI);
            bnsc[c] = sc;
            bnsh[c] = at_b[s * 512 + c] - at_m[s * 512 + c] * sc;
        }
        // GEMM3: z = bn(h_a @ atW[s]) * prior, written into xs (z buffer)
        for (int half = 0; half < 2; half++) {
            const int cbase = half * 256;
            gemm_tile<64>(hg + 64, 128, atW + s * 64 * 512 + cbase, 512, wbuf,
                [&](int m0, int c0, float (&acc)[4][8]) {
#pragma unroll
                    for (int r = 0; r < 4; r++)
#pragma unroll
                        for (int t = 0; t < 4; t++) {
                            int col = cbase + c0 + t;
                            float z = fmaf(acc[r][t], bnsc[col], bnsh[col]);
                            float p = (s == 0) ? 1.f : prior[(m0 + r) * 512 + col];
                            xs[(m0 + r) * 512 + col] = z * p;
                            int col2 = cbase + c0 + 128 + t;
                            float z2 = fmaf(acc[r][4 + t], bnsc[col2], bnsh[col2]);
                            float p2 = (s == 0) ? 1.f : prior[(m0 + r) * 512 + col2];
                            xs[(m0 + r) * 512 + col2] = z2 * p2;
                        }
                });
        }
        __syncthreads();

        // sparsemax (Newton on tau) + prior update; warp w handles rows 4w..4w+3
        {
            const int wid = tid >> 5, lane = tid & 31;
            const int mm0 = wid << 2;
            for (int r = 0; r < 4; r++) {
                const int row = mm0 + r;
                const float4* zp = reinterpret_cast<const float4*>(xs + row * 512);
                float4 zv[4];
#pragma unroll
                for (int j = 0; j < 4; j++) zv[j] = zp[lane + 32 * j];
                float ssum = 0.f;
#pragma unroll
                for (int j = 0; j < 4; j++) ssum += zv[j].x + zv[j].y + zv[j].z + zv[j].w;
#pragma unroll
                for (int off = 16; off; off >>= 1)
                    ssum += __shfl_xor_sync(0xffffffffu, ssum, off);
                // tau0 = (sum-1)/n  ->  f(tau0) >= 0, Newton ascends monotonically to root
                float tau = (ssum - 1.f) * (1.f / 512.f);
                for (int it = 0; it < 64; it++) {
                    float sb = 0.f, cb = 0.f;
#pragma unroll
                    for (int j = 0; j < 4; j++) {
                        float d;
                        d = zv[j].x - tau; if (d > 0.f) { sb += d; cb += 1.f; }
                        d = zv[j].y - tau; if (d > 0.f) { sb += d; cb += 1.f; }
                        d = zv[j].z - tau; if (d > 0.f) { sb += d; cb += 1.f; }
                        d = zv[j].w - tau; if (d > 0.f) { sb += d; cb += 1.f; }
                    }
#pragma unroll
                    for (int off = 16; off; off >>= 1) {
                        sb += __shfl_xor_sync(0xffffffffu, sb, off);
                        cb += __shfl_xor_sync(0xffffffffu, cb, off);
                    }
                    float tn = tau + (sb - 1.f) / cb;
                    if (!(tn > tau)) break;
                    tau = tn;
                }
                // prior_new = prior * (GAMMA - max(z - tau, 0))
                float4* pp = reinterpret_cast<float4*>(prior + row * 512);
#pragma unroll
                for (int j = 0; j < 4; j++) {
                    float4 pv = (s == 0) ? make_float4(1.f, 1.f, 1.f, 1.f)
                                         : pp[lane + 32 * j];
                    float4 o;
                    o.x = pv.x * (GAMMA_C - fmaxf(zv[j].x - tau, 0.f));
                    o.y = pv.y * (GAMMA_C - fmaxf(zv[j].y - tau, 0.f));
                    o.z = pv.z * (GAMMA_C - fmaxf(zv[j].z - tau, 0.f));
                    o.w = pv.w * (GAMMA_C - fmaxf(zv[j].w - tau, 0.f));
                    pp[lane + 32 * j] = o;
                }
            }
        }
        __syncthreads();
    }

    __syncthreads();
    // final: out = agg @ fW + fb   (32 rows x 2 cols)
    if (tid < 64) {
        int m = tid >> 1, o = tid & 1;
        float acc = fb[o];
#pragma unroll
        for (int j = 0; j < 64; j++) acc = fmaf(aggs[m * 64 + j], fW[j * 2 + o], acc);
        out[(size_t)(row0 + m) * 2 + o] = acc;
    }
}

extern "C" void kernel_launch(void* const* d_in, const int* in_sizes, int n_in,
                              void* d_out, int out_size)
{
    const float* x    = (const float*)d_in[0];
    const float* bn0g = (const float*)d_in[1];
    const float* bn0b = (const float*)d_in[2];
    const float* bn0m = (const float*)d_in[3];
    const float* bn0v = (const float*)d_in[4];
    const float* shW  = (const float*)d_in[5];
    const float* shg  = (const float*)d_in[6];
    const float* shbp = (const float*)d_in[7];
    const float* shm  = (const float*)d_in[8];
    const float* shv  = (const float*)d_in[9];
    const float* stW  = (const float*)d_in[10];
    const float* stg  = (const float*)d_in[11];
    const float* stb  = (const float*)d_in[12];
    const float* stm  = (const float*)d_in[13];
    const float* stv  = (const float*)d_in[14];
    const float* atW  = (const float*)d_in[15];
    const float* atg  = (const float*)d_in[16];
    const float* atb  = (const float*)d_in[17];
    const float* atm  = (const float*)d_in[18];
    const float* atv  = (const float*)d_in[19];
    const float* fW   = (const float*)d_in[20];
    const float* fb   = (const float*)d_in[21];

    int Btot = in_sizes[0] / 512;
    int grid = Btot / 32;
    size_t smem = 52224 * sizeof(float);
    cudaFuncSetAttribute(tabnet_kernel,
                         cudaFuncAttributeMaxDynamicSharedMemorySize, (int)smem);
    tabnet_kernel<<<grid, 256, smem>>>(
        x, bn0g, bn0b, bn0m, bn0v,
        shW, shg, shbp, shm, shv,
        stW, stg, stb, stm, stv,
        atW, atg, atb, atm, atv,
        fW, fb, (float*)d_out);
}

// round 3
// speedup vs baseline: 1.1376x; 1.1376x over previous
#include <cuda_runtime.h>
#include <cstdint>
#include <math.h>

#define EPSI 1e-5f
#define GAMMA_C 1.3f

typedef unsigned long long u64t;

__device__ __forceinline__ u64t splat2(float a) {
    u64t r; asm("mov.b64 %0, {%1, %1};" : "=l"(r) : "f"(a)); return r;
}
__device__ __forceinline__ void fma2(u64t& d, u64t a, u64t b) {
    asm("fma.rn.f32x2 %0, %1, %2, %0;" : "+l"(d) : "l"(a), "l"(b));
}
__device__ __forceinline__ void unpack2(u64t v, float& lo, float& hi) {
    asm("mov.b64 {%0, %1}, %2;" : "=f"(lo), "=f"(hi) : "l"(v));
}
__device__ __forceinline__ void cp16(unsigned int dst, const void* src) {
    asm volatile("cp.async.cg.shared.global [%0], [%1], 16;" :: "r"(dst), "l"(src));
}

__device__ __forceinline__ float f4c(const float4& v, int i) {
    switch (i & 3) {
        case 0: return v.x;
        case 1: return v.y;
        case 2: return v.z;
        default: return v.w;
    }
}

// Block GEMM: C[32 x 256] = A[32 x KTOT] (smem, stride lda) * W[KTOT x 256]
// (global, row stride ldw). 256 threads.
// Warp grid: rg = wid>>2 (16 rows each), cg = wid&3 (32 base cols each).
// Lane grid: rp = lane&3 (rows rbase, rbase+4, +8, +12), cp = lane>>2 (8 col-pos).
// Thread owns 4 rows x 8 cols: cols {c0..c0+3, c0+128..c0+131} (GLU pairs in-thread).
// Inner loop uses packed fma.rn.f32x2 (2 FMA per fma-pipe issue).
template <int KTOT, typename Epi>
__device__ __forceinline__ void gemm_tile(
    const float* __restrict__ As, int lda,
    const float* __restrict__ Wg, int ldw,
    float* __restrict__ wbuf, Epi epi)
{
    const int tid  = threadIdx.x;
    const int wid  = tid >> 5, lane = tid & 31;
    const int rg   = wid >> 2, cg = wid & 3;
    const int rp   = lane & 3, cp = lane >> 2;
    const int c0   = cg * 32 + cp * 4;
    const int rbase = rg * 16 + rp;
    constexpr int NCH = KTOT / 16;

    u64t acc[4][4];
#pragma unroll
    for (int i = 0; i < 4; i++)
#pragma unroll
        for (int j = 0; j < 4; j++) acc[i][j] = 0ull;

    const unsigned int wb_s = (unsigned int)__cvta_generic_to_shared(wbuf);

    // prefetch chunk 0 (16 rows x 256 cols = 1024 float4, 4 per thread)
#pragma unroll
    for (int i2 = 0; i2 < 4; i2++) {
        int f2 = tid + 256 * i2;
        int k = f2 >> 6, c = f2 & 63;
        cp16(wb_s + f2 * 16, Wg + k * ldw + c * 4);
    }
    asm volatile("cp.async.commit_group;" ::: "memory");
    asm volatile("cp.async.wait_group 0;" ::: "memory");
    __syncthreads();

    int cur = 0;
    for (int ch = 0; ch < NCH; ch++) {
        const bool more = (ch + 1 < NCH);
        if (more) {
            const float* Wn = Wg + (ch + 1) * 16 * ldw;
#pragma unroll
            for (int i2 = 0; i2 < 4; i2++) {
                int f2 = tid + 256 * i2;
                int k = f2 >> 6, c = f2 & 63;
                cp16(wb_s + (cur ^ 1) * 16384 + f2 * 16, Wn + k * ldw + c * 4);
            }
            asm volatile("cp.async.commit_group;" ::: "memory");
        }
        const float* wc = wbuf + cur * 4096;
        const int kk = ch * 16;
#pragma unroll
        for (int k4 = 0; k4 < 4; k4++) {
            float4 a[4];
#pragma unroll
            for (int i = 0; i < 4; i++)
                a[i] = *reinterpret_cast<const float4*>(
                    As + (rbase + 4 * i) * lda + kk + k4 * 4);
#pragma unroll
            for (int kz = 0; kz < 4; kz++) {
                const float* wr = wc + (k4 * 4 + kz) * 256;
                ulonglong2 w0 = *reinterpret_cast<const ulonglong2*>(wr + c0);
                ulonglong2 w1 = *reinterpret_cast<const ulonglong2*>(wr + c0 + 128);
#pragma unroll
                for (int i = 0; i < 4; i++) {
                    u64t s = splat2(f4c(a[i], kz));
                    fma2(acc[i][0], s, w0.x);
                    fma2(acc[i][1], s, w0.y);
                    fma2(acc[i][2], s, w1.x);
                    fma2(acc[i][3], s, w1.y);
                }
            }
        }
        if (more) asm volatile("cp.async.wait_group 0;" ::: "memory");
        __syncthreads();
        cur ^= 1;
    }
    epi(rbase, c0, acc);
}

#define XS_LD 516
#define SH_LD 132

__global__ __launch_bounds__(256, 1)
void tabnet_kernel(
    const float* __restrict__ x,
    const float* __restrict__ bn0_g, const float* __restrict__ bn0_b,
    const float* __restrict__ bn0_m, const float* __restrict__ bn0_v,
    const float* __restrict__ shW,
    const float* __restrict__ sh_g, const float* __restrict__ sh_b,
    const float* __restrict__ sh_m, const float* __restrict__ sh_v,
    const float* __restrict__ stW,
    const float* __restrict__ st_g, const float* __restrict__ st_b,
    const float* __restrict__ st_m, const float* __restrict__ st_v,
    const float* __restrict__ atW,
    const float* __restrict__ at_g, const float* __restrict__ at_b,
    const float* __restrict__ at_m, const float* __restrict__ at_v,
    const float* __restrict__ fW, const float* __restrict__ fb,
    float* __restrict__ out)
{
    extern __shared__ float smem[];
    float* xs    = smem;             // [32][516]  x tile, later z buffer
    float* prior = smem + 16512;     // [32][512]
    float* shb   = smem + 32896;     // [32][132]  GLU(shared step) output
    float* hg    = smem + 37120;     // [32][132]  GLU(step) output (h_d | h_a)
    float* aggs  = smem + 41344;     // [32][64]
    float* wbuf  = smem + 43392;     // 2 x [16][256] weight chunks
    float* bnsc  = smem + 51584;     // [512]
    float* bnsh  = smem + 52096;     // [512]
    // total 52608 floats = 210432 bytes

    const int tid = threadIdx.x;
    const int row0 = blockIdx.x << 5;

    for (int i = tid; i < 2048; i += 256) aggs[i] = 0.f;

    for (int c = tid; c < 512; c += 256) {
        float sc = bn0_g[c] * rsqrtf(bn0_v[c] + EPSI);
        bnsc[c] = sc;
        bnsh[c] = bn0_b[c] - bn0_m[c] * sc;
    }
    __syncthreads();

    // load x tile + bn0
    {
        const float4* xg = reinterpret_cast<const float4*>(x) + (size_t)row0 * 128;
        const float4* s4 = reinterpret_cast<const float4*>(bnsc);
        const float4* b4 = reinterpret_cast<const float4*>(bnsh);
        float4* xs4 = reinterpret_cast<float4*>(xs);
#pragma unroll
        for (int i = 0; i < 16; i++) {
            int f = tid + 256 * i;
            int r = f >> 7, c4 = f & 127;
            float4 v = xg[f];
            float4 s = s4[c4], b = b4[c4];
            v.x = fmaf(v.x, s.x, b.x);
            v.y = fmaf(v.y, s.y, b.y);
            v.z = fmaf(v.z, s.z, b.z);
            v.w = fmaf(v.w, s.w, b.w);
            xs4[r * 129 + c4] = v;
        }
    }
    __syncthreads();

    // shared-step bn tables
    {
        int c = tid;
        float sc = sh_g[c] * rsqrtf(sh_v[c] + EPSI);
        bnsc[c] = sc;
        bnsh[c] = sh_b[c] - sh_m[c] * sc;
    }

    // GEMM1: sh = GLU(bn(x @ shW))
    gemm_tile<512>(xs, XS_LD, shW, 256, wbuf,
        [&](int rb, int c0, u64t (&acc)[4][4]) {
#pragma unroll
            for (int i = 0; i < 4; i++) {
                int row = rb + 4 * i;
                float u[4], w[4];
                unpack2(acc[i][0], u[0], u[1]);
                unpack2(acc[i][1], u[2], u[3]);
                unpack2(acc[i][2], w[0], w[1]);
                unpack2(acc[i][3], w[2], w[3]);
#pragma unroll
                for (int t = 0; t < 4; t++) {
                    int cu = c0 + t, cw = c0 + 128 + t;
                    float uu = fmaf(u[t], bnsc[cu], bnsh[cu]);
                    float ww = fmaf(w[t], bnsc[cw], bnsh[cw]);
                    shb[row * SH_LD + cu] = uu / (1.f + __expf(-ww));
                }
            }
        });
    __syncthreads();

    for (int s = 0; s < 3; s++) {
        {
            int c = tid;
            float sc = st_g[s * 256 + c] * rsqrtf(st_v[s * 256 + c] + EPSI);
            bnsc[c] = sc;
            bnsh[c] = st_b[s * 256 + c] - st_m[s * 256 + c] * sc;
        }
        // GEMM2: h = GLU(bn(sh @ stW[s])); agg += h_d
        gemm_tile<128>(shb, SH_LD, stW + s * 128 * 256, 256, wbuf,
            [&](int rb, int c0, u64t (&acc)[4][4]) {
#pragma unroll
                for (int i = 0; i < 4; i++) {
                    int row = rb + 4 * i;
                    float u[4], w[4];
                    unpack2(acc[i][0], u[0], u[1]);
                    unpack2(acc[i][1], u[2], u[3]);
                    unpack2(acc[i][2], w[0], w[1]);
                    unpack2(acc[i][3], w[2], w[3]);
#pragma unroll
                    for (int t = 0; t < 4; t++) {
                        int cu = c0 + t, cw = c0 + 128 + t;
                        float uu = fmaf(u[t], bnsc[cu], bnsh[cu]);
                        float ww = fmaf(w[t], bnsc[cw], bnsh[cw]);
                        float val = uu / (1.f + __expf(-ww));
                        hg[row * SH_LD + cu] = val;
                        if (c0 < 64) aggs[row * 64 + cu] += val;
                    }
                }
            });
        __syncthreads();
        if (s == 2) break;  // last step's attention/sparsemax/prior are dead code

        for (int c = tid; c < 512; c += 256) {
            float sc = at_g[s * 512 + c] * rsqrtf(at_v[s * 512 + c] + EPSI);
            bnsc[c] = sc;
            bnsh[c] = at_b[s * 512 + c] - at_m[s * 512 + c] * sc;
        }
        // GEMM3: z = bn(h_a @ atW[s]) * prior -> xs
        for (int half = 0; half < 2; half++) {
            const int cbase = half * 256;
            gemm_tile<64>(hg + 64, SH_LD, atW + s * 64 * 512 + cbase, 512, wbuf,
                [&](int rb, int c0, u64t (&acc)[4][4]) {
#pragma unroll
                    for (int i = 0; i < 4; i++) {
                        int row = rb + 4 * i;
                        float u[4], w[4];
                        unpack2(acc[i][0], u[0], u[1]);
                        unpack2(acc[i][1], u[2], u[3]);
                        unpack2(acc[i][2], w[0], w[1]);
                        unpack2(acc[i][3], w[2], w[3]);
#pragma unroll
                        for (int t = 0; t < 4; t++) {
                            int col = cbase + c0 + t;
                            float z = fmaf(u[t], bnsc[col], bnsh[col]);
                            float p = (s == 0) ? 1.f : prior[row * 512 + col];
                            xs[row * XS_LD + col] = z * p;
                            int col2 = cbase + c0 + 128 + t;
                            float z2 = fmaf(w[t], bnsc[col2], bnsh[col2]);
                            float p2 = (s == 0) ? 1.f : prior[row * 512 + col2];
                            xs[row * XS_LD + col2] = z2 * p2;
                        }
                    }
                });
        }
        __syncthreads();

        // sparsemax (Newton on tau) + prior update; warp w -> rows 4w..4w+3
        {
            const int wid = tid >> 5, lane = tid & 31;
            const int mm0 = wid << 2;
            for (int r = 0; r < 4; r++) {
                const int row = mm0 + r;
                const float4* zp = reinterpret_cast<const float4*>(xs + row * XS_LD);
                float4 zv[4];
#pragma unroll
                for (int j = 0; j < 4; j++) zv[j] = zp[lane + 32 * j];
                float ssum = 0.f;
#pragma unroll
                for (int j = 0; j < 4; j++) ssum += zv[j].x + zv[j].y + zv[j].z + zv[j].w;
#pragma unroll
                for (int off = 16; off; off >>= 1)
                    ssum += __shfl_xor_sync(0xffffffffu, ssum, off);
                float tau = (ssum - 1.f) * (1.f / 512.f);
                for (int it = 0; it < 64; it++) {
                    float sb = 0.f, cb = 0.f;
#pragma unroll
                    for (int j = 0; j < 4; j++) {
                        float d;
                        d = zv[j].x - tau; if (d > 0.f) { sb += d; cb += 1.f; }
                        d = zv[j].y - tau; if (d > 0.f) { sb += d; cb += 1.f; }
                        d = zv[j].z - tau; if (d > 0.f) { sb += d; cb += 1.f; }
                        d = zv[j].w - tau; if (d > 0.f) { sb += d; cb += 1.f; }
                    }
#pragma unroll
                    for (int off = 16; off; off >>= 1) {
                        sb += __shfl_xor_sync(0xffffffffu, sb, off);
                        cb += __shfl_xor_sync(0xffffffffu, cb, off);
                    }
                    float tn = tau + (sb - 1.f) / cb;
                    if (!(tn > tau)) break;
                    tau = tn;
                }
                float4* pp = reinterpret_cast<float4*>(prior + row * 512);
#pragma unroll
                for (int j = 0; j < 4; j++) {
                    float4 pv = (s == 0) ? make_float4(1.f, 1.f, 1.f, 1.f)
                                         : pp[lane + 32 * j];
                    float4 o;
                    o.x = pv.x * (GAMMA_C - fmaxf(zv[j].x - tau, 0.f));
                    o.y = pv.y * (GAMMA_C - fmaxf(zv[j].y - tau, 0.f));
                    o.z = pv.z * (GAMMA_C - fmaxf(zv[j].z - tau, 0.f));
                    o.w = pv.w * (GAMMA_C - fmaxf(zv[j].w - tau, 0.f));
                    pp[lane + 32 * j] = o;
                }
            }
        }
        __syncthreads();
    }

    __syncthreads();
    // final: out = agg @ fW + fb
    if (tid < 64) {
        int m = tid >> 1, o = tid & 1;
        float acc = fb[o];
#pragma unroll
        for (int j = 0; j < 64; j++) acc = fmaf(aggs[m * 64 + j], fW[j * 2 + o], acc);
        out[(size_t)(row0 + m) * 2 + o] = acc;
    }
}

extern "C" void kernel_launch(void* const* d_in, const int* in_sizes, int n_in,
                              void* d_out, int out_size)
{
    const float* x    = (const float*)d_in[0];
    const float* bn0g = (const float*)d_in[1];
    const float* bn0b = (const float*)d_in[2];
    const float* bn0m = (const float*)d_in[3];
    const float* bn0v = (const float*)d_in[4];
    const float* shW  = (const float*)d_in[5];
    const float* shg  = (const float*)d_in[6];
    const float* shbp = (const float*)d_in[7];
    const float* shm  = (const float*)d_in[8];
    const float* shv  = (const float*)d_in[9];
    const float* stW  = (const float*)d_in[10];
    const float* stg  = (const float*)d_in[11];
    const float* stb  = (const float*)d_in[12];
    const float* stm  = (const float*)d_in[13];
    const float* stv  = (const float*)d_in[14];
    const float* atW  = (const float*)d_in[15];
    const float* atg  = (const float*)d_in[16];
    const float* atb  = (const float*)d_in[17];
    const float* atm  = (const float*)d_in[18];
    const float* atv  = (const float*)d_in[19];
    const float* fW   = (const float*)d_in[20];
    const float* fb   = (const float*)d_in[21];

    int Btot = in_sizes[0] / 512;
    int grid = Btot / 32;
    size_t smem = 52608 * sizeof(float);
    cudaFuncSetAttribute(tabnet_kernel,
                         cudaFuncAttributeMaxDynamicSharedMemorySize, (int)smem);
    tabnet_kernel<<<grid, 256, smem>>>(
        x, bn0g, bn0b, bn0m, bn0v,
        shW, shg, shbp, shm, shv,
        stW, stg, stb, stm, stv,
        atW, atg, atb, atm, atv,
        fW, fb, (float*)d_out);
}